// round 7
// baseline (speedup 1.0000x reference)
#include <cuda_runtime.h>
#include <math.h>
#include <cstdint>

#define B_   8
#define H_   16
#define L_   512
#define DIM_ 1024
#define HD_  64

// Scratch (device globals: allocation-free per harness rules)
__device__ __align__(16) float g_Q [B_ * L_ * DIM_];
__device__ __align__(16) float g_K [B_ * L_ * DIM_];
__device__ __align__(16) float g_V [B_ * L_ * DIM_];
__device__ __align__(16) float g_AO[B_ * L_ * DIM_];

// ===========================================================================
// helpers (baseline PTX, supported on compute_103)
// ===========================================================================
__device__ __forceinline__ uint32_t f2tf32(float f) {
    uint32_t o;
    asm("cvt.rna.tf32.f32 %0, %1;" : "=r"(o) : "f"(f));
    return o;
}

__device__ __forceinline__ void mma_tf32(
    float& d0, float& d1, float& d2, float& d3,
    uint32_t a0, uint32_t a1, uint32_t a2, uint32_t a3,
    uint32_t b0, uint32_t b1)
{
    asm volatile(
        "mma.sync.aligned.m16n8k8.row.col.f32.tf32.tf32.f32 "
        "{%0,%1,%2,%3}, {%4,%5,%6,%7}, {%8,%9}, {%0,%1,%2,%3};"
        : "+f"(d0), "+f"(d1), "+f"(d2), "+f"(d3)
        : "r"(a0), "r"(a1), "r"(a2), "r"(a3), "r"(b0), "r"(b1));
}

__device__ __forceinline__ uint32_t smem_u32(const void* p) {
    uint32_t a;
    asm("{ .reg .u64 t; cvta.to.shared.u64 t, %1; cvt.u32.u64 %0, t; }"
        : "=r"(a) : "l"(p));
    return a;
}

#define CP_ASYNC16(dst_u32, src_ptr) \
    asm volatile("cp.async.cg.shared.global [%0], [%1], 16;" \
        :: "r"(dst_u32), "l"(src_ptr))
#define CP_COMMIT() asm volatile("cp.async.commit_group;" ::: "memory")
#define CP_WAIT0()  asm volatile("cp.async.wait_group 0;" ::: "memory")

// ===========================================================================
// Projection GEMM v3: cp.async staging (fp32 in SMEM), cvt at fragment load.
// C[M,1024] = A[M,1024] @ W[1024,1024]^T + bias
// CTA tile 128x128, 4 warps (2m x 2n), warp tile 64x64. KB=16, 2-stage.
// mode 0: fused QKV (z=0 Q, z=1 K, z=2 V), mode 1: output proj -> C_ext
// ===========================================================================
#define GK    1024
#define KB    16
#define NCH   (GK / KB)
#define SST   20

__global__ __launch_bounds__(128, 2) void gemm_tf32_mma(
    const float* __restrict__ seq1, const float* __restrict__ seq2,
    const float* __restrict__ Wq, const float* __restrict__ bq,
    const float* __restrict__ Wk, const float* __restrict__ bk,
    const float* __restrict__ Wv, const float* __restrict__ bv,
    float* __restrict__ C_ext, int mode)
{
    const float* A;
    const float* W;
    const float* bias;
    float* C;
    if (mode == 1) {
        A = (const float*)g_AO; W = Wq; bias = bq; C = C_ext;
    } else {
        const int z = blockIdx.z;
        if (z == 0)      { A = seq1; W = Wq; bias = bq; C = g_Q; }
        else if (z == 1) { A = seq2; W = Wk; bias = bk; C = g_K; }
        else             { A = seq2; W = Wv; bias = bv; C = g_V; }
    }

    __shared__ __align__(16) float As[2][128 * SST];
    __shared__ __align__(16) float Bs[2][128 * SST];
    __shared__ float s_bias[128];

    const int tid  = threadIdx.x;
    const int wid  = tid >> 5;
    const int lane = tid & 31;
    const int g    = lane >> 2;
    const int tg   = lane & 3;
    const int mrow = (wid >> 1) * 64;
    const int ncol = (wid & 1) * 64;

    const float* Arow = A + (size_t)blockIdx.y * 128 * GK;
    const float* Wrow = W + (size_t)blockIdx.x * 128 * GK;

    if (tid < 128) s_bias[tid] = bias[blockIdx.x * 128 + tid];

    // copy slots: 512 float4 per tile per stage, 4 per thread per tile
    int rL[4], kL[4];
#pragma unroll
    for (int t = 0; t < 4; t++) {
        const int s = tid + t * 128;
        rL[t] = s >> 2;
        kL[t] = (s & 3) << 2;
    }
    uint32_t asu[2], bsu[2];
    asu[0] = smem_u32(&As[0][0]); asu[1] = smem_u32(&As[1][0]);
    bsu[0] = smem_u32(&Bs[0][0]); bsu[1] = smem_u32(&Bs[1][0]);

    float acc[4][8][4];
#pragma unroll
    for (int mt = 0; mt < 4; mt++)
#pragma unroll
        for (int nt = 0; nt < 8; nt++)
#pragma unroll
            for (int e = 0; e < 4; e++) acc[mt][nt][e] = 0.f;

    // Prologue: chunk 0 -> stage 0
#pragma unroll
    for (int t = 0; t < 4; t++) {
        const uint32_t so = (uint32_t)(rL[t] * SST + kL[t]) * 4u;
        CP_ASYNC16(asu[0] + so, Arow + (size_t)rL[t] * GK + kL[t]);
        CP_ASYNC16(bsu[0] + so, Wrow + (size_t)rL[t] * GK + kL[t]);
    }
    CP_COMMIT();

    for (int i = 0; i < NCH; i++) {
        const int st = i & 1;
        CP_WAIT0();
        __syncthreads();   // stage st data visible; prior compute on ns done

        if (i + 1 < NCH) {
            const int ns = st ^ 1;
            const int ko = (i + 1) * KB;
#pragma unroll
            for (int t = 0; t < 4; t++) {
                const uint32_t so = (uint32_t)(rL[t] * SST + kL[t]) * 4u;
                CP_ASYNC16(asu[ns] + so, Arow + (size_t)rL[t] * GK + ko + kL[t]);
                CP_ASYNC16(bsu[ns] + so, Wrow + (size_t)rL[t] * GK + ko + kL[t]);
            }
            CP_COMMIT();
        }

#pragma unroll
        for (int ks = 0; ks < 2; ks++) {
            uint32_t a[4][4];
#pragma unroll
            for (int mt = 0; mt < 4; mt++) {
                const int rb = mrow + mt * 16 + g;
                a[mt][0] = f2tf32(As[st][(rb)     * SST + ks * 8 + tg]);
                a[mt][1] = f2tf32(As[st][(rb + 8) * SST + ks * 8 + tg]);
                a[mt][2] = f2tf32(As[st][(rb)     * SST + ks * 8 + tg + 4]);
                a[mt][3] = f2tf32(As[st][(rb + 8) * SST + ks * 8 + tg + 4]);
            }
#pragma unroll
            for (int nt = 0; nt < 8; nt++) {
                const int rw = ncol + nt * 8 + g;
                uint32_t b0 = f2tf32(Bs[st][rw * SST + ks * 8 + tg]);
                uint32_t b1 = f2tf32(Bs[st][rw * SST + ks * 8 + tg + 4]);
#pragma unroll
                for (int mt = 0; mt < 4; mt++)
                    mma_tf32(acc[mt][nt][0], acc[mt][nt][1], acc[mt][nt][2], acc[mt][nt][3],
                             a[mt][0], a[mt][1], a[mt][2], a[mt][3], b0, b1);
            }
        }
    }

#pragma unroll
    for (int mt = 0; mt < 4; mt++) {
#pragma unroll
        for (int nt = 0; nt < 8; nt++) {
            const int row = mrow + mt * 16 + g;
            const int col = ncol + nt * 8 + 2 * tg;
            const int gm0 = blockIdx.y * 128 + row;
            const int gc  = blockIdx.x * 128 + col;
            float2 o;
            o.x = acc[mt][nt][0] + s_bias[col];
            o.y = acc[mt][nt][1] + s_bias[col + 1];
            *(float2*)(C + (size_t)gm0 * DIM_ + gc) = o;
            o.x = acc[mt][nt][2] + s_bias[col];
            o.y = acc[mt][nt][3] + s_bias[col + 1];
            *(float2*)(C + (size_t)(gm0 + 8) * DIM_ + gc) = o;
        }
    }
}

// ===========================================================================
// Fused attention (unchanged, known-passing):
// QK^T -> dual online softmax (+Atchley bias) -> mix -> @V, output -> g_AO
// ===========================================================================
#define KST 68
#define VST 72

__global__ __launch_bounds__(256) void attn_fused_kernel(
    const float* __restrict__ atc1, const float* __restrict__ atc2,
    const float* __restrict__ U, const float* __restrict__ mixp)
{
    const int bh = blockIdx.y;
    const int b  = bh >> 4;
    const int h  = bh & 15;
    const int i0 = blockIdx.x * 128;

    __shared__ uint32_t KVs[64 * VST];
    __shared__ float Atc2s[64][5];

    const int tid  = threadIdx.x;
    const int wid  = tid >> 5;
    const int lane = tid & 31;
    const int g    = lane >> 2;
    const int tg   = lane & 3;
    const int wrow = wid * 16;

    uint32_t qf[8][4];
    {
        const float* Qb = g_Q + (size_t)(b * L_ + i0 + wrow) * DIM_ + h * HD_;
#pragma unroll
        for (int kb = 0; kb < 8; kb++) {
            qf[kb][0] = f2tf32(__ldg(Qb + (size_t)g       * DIM_ + kb * 8 + tg));
            qf[kb][1] = f2tf32(__ldg(Qb + (size_t)(g + 8) * DIM_ + kb * 8 + tg));
            qf[kb][2] = f2tf32(__ldg(Qb + (size_t)g       * DIM_ + kb * 8 + tg + 4));
            qf[kb][3] = f2tf32(__ldg(Qb + (size_t)(g + 8) * DIM_ + kb * 8 + tg + 4));
        }
    }

    float a1u0[5], a1u8[5];
    {
        const float* a1p = atc1 + (size_t)(b * L_ + i0 + wrow + g) * 5;
        float a1_0[5], a1_8[5];
#pragma unroll
        for (int p = 0; p < 5; p++) {
            a1_0[p] = __ldg(a1p + p);
            a1_8[p] = __ldg(a1p + 40 + p);
        }
#pragma unroll
        for (int q = 0; q < 5; q++) {
            float s0 = 0.f, s8 = 0.f;
#pragma unroll
            for (int p = 0; p < 5; p++) {
                float u = __ldg(&U[h * 25 + p * 5 + q]);
                s0 = fmaf(a1_0[p], u, s0);
                s8 = fmaf(a1_8[p], u, s8);
            }
            a1u0[q] = s0;
            a1u8[q] = s8;
        }
    }

    float m1[2] = {-1e30f, -1e30f}, l1[2] = {0.f, 0.f};
    float m2[2] = {-1e30f, -1e30f}, l2[2] = {0.f, 0.f};
    float O1[8][4], O2[8][4];
#pragma unroll
    for (int nb = 0; nb < 8; nb++)
#pragma unroll
        for (int e = 0; e < 4; e++) { O1[nb][e] = 0.f; O2[nb][e] = 0.f; }

    for (int ch = 0; ch < 8; ch++) {
        const int j0 = ch * 64;
        __syncthreads();

#pragma unroll
        for (int t = 0; t < 4; t++) {
            const int s  = tid + t * 256;
            const int r  = s >> 4;
            const int c4 = (s & 15) << 2;
            float4 k = *(const float4*)&g_K[(size_t)(b * L_ + j0 + r) * DIM_ + h * HD_ + c4];
            uint4 u;
            u.x = f2tf32(k.x); u.y = f2tf32(k.y); u.z = f2tf32(k.z); u.w = f2tf32(k.w);
            *(uint4*)&KVs[r * KST + c4] = u;
        }
        if (tid < 64) {
#pragma unroll
            for (int q = 0; q < 5; q++)
                Atc2s[tid][q] = __ldg(&atc2[(size_t)(b * L_ + j0 + tid) * 5 + q]);
        }
        __syncthreads();

        float s1[8][4];
#pragma unroll
        for (int nt = 0; nt < 8; nt++)
#pragma unroll
            for (int e = 0; e < 4; e++) s1[nt][e] = 0.f;
#pragma unroll
        for (int kb = 0; kb < 8; kb++) {
#pragma unroll
            for (int nt = 0; nt < 8; nt++) {
                uint32_t b0 = KVs[(nt * 8 + g) * KST + kb * 8 + tg];
                uint32_t b1 = KVs[(nt * 8 + g) * KST + kb * 8 + tg + 4];
                mma_tf32(s1[nt][0], s1[nt][1], s1[nt][2], s1[nt][3],
                         qf[kb][0], qf[kb][1], qf[kb][2], qf[kb][3], b0, b1);
            }
        }
        float s2[8][4];
#pragma unroll
        for (int nt = 0; nt < 8; nt++) {
            const int c0 = nt * 8 + 2 * tg;
            float d00 = 0.f, d01 = 0.f, d80 = 0.f, d81 = 0.f;
#pragma unroll
            for (int q = 0; q < 5; q++) {
                float a20 = Atc2s[c0][q];
                float a21 = Atc2s[c0 + 1][q];
                d00 = fmaf(a1u0[q], a20, d00);
                d01 = fmaf(a1u0[q], a21, d01);
                d80 = fmaf(a1u8[q], a20, d80);
                d81 = fmaf(a1u8[q], a21, d81);
            }
            s2[nt][0] = d00; s2[nt][1] = d01; s2[nt][2] = d80; s2[nt][3] = d81;
#pragma unroll
            for (int e = 0; e < 4; e++) s1[nt][e] *= 0.125f;
        }

        float cm1g = -1e30f, cm1h = -1e30f, cm2g = -1e30f, cm2h = -1e30f;
#pragma unroll
        for (int nt = 0; nt < 8; nt++) {
            cm1g = fmaxf(cm1g, fmaxf(s1[nt][0], s1[nt][1]));
            cm1h = fmaxf(cm1h, fmaxf(s1[nt][2], s1[nt][3]));
            cm2g = fmaxf(cm2g, fmaxf(s2[nt][0], s2[nt][1]));
            cm2h = fmaxf(cm2h, fmaxf(s2[nt][2], s2[nt][3]));
        }
#pragma unroll
        for (int o = 1; o <= 2; o <<= 1) {
            cm1g = fmaxf(cm1g, __shfl_xor_sync(0xffffffffu, cm1g, o));
            cm1h = fmaxf(cm1h, __shfl_xor_sync(0xffffffffu, cm1h, o));
            cm2g = fmaxf(cm2g, __shfl_xor_sync(0xffffffffu, cm2g, o));
            cm2h = fmaxf(cm2h, __shfl_xor_sync(0xffffffffu, cm2h, o));
        }

        float nm, al;
        nm = fmaxf(m1[0], cm1g); al = __expf(m1[0] - nm); m1[0] = nm; l1[0] *= al;
#pragma unroll
        for (int nb = 0; nb < 8; nb++) { O1[nb][0] *= al; O1[nb][1] *= al; }
        nm = fmaxf(m1[1], cm1h); al = __expf(m1[1] - nm); m1[1] = nm; l1[1] *= al;
#pragma unroll
        for (int nb = 0; nb < 8; nb++) { O1[nb][2] *= al; O1[nb][3] *= al; }
        nm = fmaxf(m2[0], cm2g); al = __expf(m2[0] - nm); m2[0] = nm; l2[0] *= al;
#pragma unroll
        for (int nb = 0; nb < 8; nb++) { O2[nb][0] *= al; O2[nb][1] *= al; }
        nm = fmaxf(m2[1], cm2h); al = __expf(m2[1] - nm); m2[1] = nm; l2[1] *= al;
#pragma unroll
        for (int nb = 0; nb < 8; nb++) { O2[nb][2] *= al; O2[nb][3] *= al; }

        float rs1g = 0.f, rs1h = 0.f, rs2g = 0.f, rs2h = 0.f;
#pragma unroll
        for (int nt = 0; nt < 8; nt++) {
            s1[nt][0] = __expf(s1[nt][0] - m1[0]); rs1g += s1[nt][0];
            s1[nt][1] = __expf(s1[nt][1] - m1[0]); rs1g += s1[nt][1];
            s1[nt][2] = __expf(s1[nt][2] - m1[1]); rs1h += s1[nt][2];
            s1[nt][3] = __expf(s1[nt][3] - m1[1]); rs1h += s1[nt][3];
            s2[nt][0] = __expf(s2[nt][0] - m2[0]); rs2g += s2[nt][0];
            s2[nt][1] = __expf(s2[nt][1] - m2[0]); rs2g += s2[nt][1];
            s2[nt][2] = __expf(s2[nt][2] - m2[1]); rs2h += s2[nt][2];
            s2[nt][3] = __expf(s2[nt][3] - m2[1]); rs2h += s2[nt][3];
        }
#pragma unroll
        for (int o = 1; o <= 2; o <<= 1) {
            rs1g += __shfl_xor_sync(0xffffffffu, rs1g, o);
            rs1h += __shfl_xor_sync(0xffffffffu, rs1h, o);
            rs2g += __shfl_xor_sync(0xffffffffu, rs2g, o);
            rs2h += __shfl_xor_sync(0xffffffffu, rs2h, o);
        }
        l1[0] += rs1g; l1[1] += rs1h;
        l2[0] += rs2g; l2[1] += rs2h;

        __syncthreads();

#pragma unroll
        for (int t = 0; t < 4; t++) {
            const int s  = tid + t * 256;
            const int r  = s >> 4;
            const int c4 = (s & 15) << 2;
            float4 v = *(const float4*)&g_V[(size_t)(b * L_ + j0 + r) * DIM_ + h * HD_ + c4];
            uint4 u;
            u.x = f2tf32(v.x); u.y = f2tf32(v.y); u.z = f2tf32(v.z); u.w = f2tf32(v.w);
            *(uint4*)&KVs[r * VST + c4] = u;
        }
        __syncthreads();

        const int srcA = (lane & ~3) | (tg >> 1);
        const int srcB = srcA + 2;
        const bool odd = (tg & 1);
#pragma unroll
        for (int kb = 0; kb < 8; kb++) {
            float p0a = __shfl_sync(0xffffffffu, s1[kb][0], srcA);
            float p1a = __shfl_sync(0xffffffffu, s1[kb][1], srcA);
            float p2a = __shfl_sync(0xffffffffu, s1[kb][2], srcA);
            float p3a = __shfl_sync(0xffffffffu, s1[kb][3], srcA);
            float p0b = __shfl_sync(0xffffffffu, s1[kb][0], srcB);
            float p1b = __shfl_sync(0xffffffffu, s1[kb][1], srcB);
            float p2b = __shfl_sync(0xffffffffu, s1[kb][2], srcB);
            float p3b = __shfl_sync(0xffffffffu, s1[kb][3], srcB);
            uint32_t A1_0 = f2tf32(odd ? p1a : p0a);
            uint32_t A1_1 = f2tf32(odd ? p3a : p2a);
            uint32_t A1_2 = f2tf32(odd ? p1b : p0b);
            uint32_t A1_3 = f2tf32(odd ? p3b : p2b);

            p0a = __shfl_sync(0xffffffffu, s2[kb][0], srcA);
            p1a = __shfl_sync(0xffffffffu, s2[kb][1], srcA);
            p2a = __shfl_sync(0xffffffffu, s2[kb][2], srcA);
            p3a = __shfl_sync(0xffffffffu, s2[kb][3], srcA);
            p0b = __shfl_sync(0xffffffffu, s2[kb][0], srcB);
            p1b = __shfl_sync(0xffffffffu, s2[kb][1], srcB);
            p2b = __shfl_sync(0xffffffffu, s2[kb][2], srcB);
            p3b = __shfl_sync(0xffffffffu, s2[kb][3], srcB);
            uint32_t A2_0 = f2tf32(odd ? p1a : p0a);
            uint32_t A2_1 = f2tf32(odd ? p3a : p2a);
            uint32_t A2_2 = f2tf32(odd ? p1b : p0b);
            uint32_t A2_3 = f2tf32(odd ? p3b : p2b);

#pragma unroll
            for (int nb = 0; nb < 8; nb++) {
                uint32_t b0 = KVs[(kb * 8 + tg)     * VST + nb * 8 + g];
                uint32_t b1 = KVs[(kb * 8 + tg + 4) * VST + nb * 8 + g];
                mma_tf32(O1[nb][0], O1[nb][1], O1[nb][2], O1[nb][3],
                         A1_0, A1_1, A1_2, A1_3, b0, b1);
                mma_tf32(O2[nb][0], O2[nb][1], O2[nb][2], O2[nb][3],
                         A2_0, A2_1, A2_2, A2_3, b0, b1);
            }
        }
    }

    const float mixr = (tanhf(__ldg(mixp)) + 1.f) * 0.5f;
    const float w1g = (1.f - mixr) / l1[0], w1h = (1.f - mixr) / l1[1];
    const float w2g = mixr / l2[0],         w2h = mixr / l2[1];
    float* Ao = g_AO + (size_t)(b * L_ + i0 + wrow) * DIM_ + h * HD_;
#pragma unroll
    for (int nb = 0; nb < 8; nb++) {
        const int col = nb * 8 + 2 * tg;
        float2 o;
        o.x = O1[nb][0] * w1g + O2[nb][0] * w2g;
        o.y = O1[nb][1] * w1g + O2[nb][1] * w2g;
        *(float2*)(Ao + (size_t)g * DIM_ + col) = o;
        o.x = O1[nb][2] * w1h + O2[nb][2] * w2h;
        o.y = O1[nb][3] * w1h + O2[nb][3] * w2h;
        *(float2*)(Ao + (size_t)(g + 8) * DIM_ + col) = o;
    }
}

// ---------------------------------------------------------------------------
extern "C" void kernel_launch(void* const* d_in, const int* in_sizes, int n_in,
                              void* d_out, int out_size)
{
    const float* seq1 = (const float*)d_in[0];
    const float* seq2 = (const float*)d_in[1];
    const float* atc1 = (const float*)d_in[2];
    const float* atc2 = (const float*)d_in[3];
    const float* Wq   = (const float*)d_in[4];
    const float* bq   = (const float*)d_in[5];
    const float* Wk   = (const float*)d_in[6];
    const float* bk   = (const float*)d_in[7];
    const float* Wv   = (const float*)d_in[8];
    const float* bv   = (const float*)d_in[9];
    const float* Wo   = (const float*)d_in[10];
    const float* bo   = (const float*)d_in[11];
    const float* U    = (const float*)d_in[12];
    const float* mixp = (const float*)d_in[13];
    float* out = (float*)d_out;

    const int M = B_ * L_;                       // 4096

    // Fused Q/K/V projections (cp.async pipeline)
    gemm_tf32_mma<<<dim3(DIM_ / 128, M / 128, 3), 128>>>(
        seq1, seq2, Wq, bq, Wk, bk, Wv, bv, nullptr, 0);

    // Fused attention (QK^T + dual softmax + Atchley bias + mix + @V)
    attn_fused_kernel<<<dim3(L_ / 128, B_ * H_), 256>>>(atc1, atc2, U, mixp);

    // Output projection -> d_out
    gemm_tf32_mma<<<dim3(DIM_ / 128, M / 128, 1), 128>>>(
        nullptr, nullptr, Wo, bo, nullptr, nullptr, nullptr, nullptr, out, 1);
}

// round 8
// speedup vs baseline: 1.1166x; 1.1166x over previous
#include <cuda_runtime.h>
#include <math.h>
#include <cstdint>

#define B_   8
#define H_   16
#define L_   512
#define DIM_ 1024
#define HD_  64

// Scratch (device globals: allocation-free per harness rules)
__device__ __align__(16) float g_Q [B_ * L_ * DIM_];
__device__ __align__(16) float g_K [B_ * L_ * DIM_];
__device__ __align__(16) float g_V [B_ * L_ * DIM_];
__device__ __align__(16) float g_AO[B_ * L_ * DIM_];

// ===========================================================================
// tf32 helpers (baseline PTX, supported on compute_103)
// ===========================================================================
__device__ __forceinline__ uint32_t f2tf32(float f) {
    uint32_t o;
    asm("cvt.rna.tf32.f32 %0, %1;" : "=r"(o) : "f"(f));
    return o;
}

__device__ __forceinline__ void mma_tf32(
    float& d0, float& d1, float& d2, float& d3,
    uint32_t a0, uint32_t a1, uint32_t a2, uint32_t a3,
    uint32_t b0, uint32_t b1)
{
    asm volatile(
        "mma.sync.aligned.m16n8k8.row.col.f32.tf32.tf32.f32 "
        "{%0,%1,%2,%3}, {%4,%5,%6,%7}, {%8,%9}, {%0,%1,%2,%3};"
        : "+f"(d0), "+f"(d1), "+f"(d2), "+f"(d3)
        : "r"(a0), "r"(a1), "r"(a2), "r"(a3), "r"(b0), "r"(b1));
}

// ===========================================================================
// Projection GEMM (round-6 version, known-best 203us for 3 GEMMs):
// C[M,1024] = A[M,1024] @ W[1024,1024]^T + bias
// CTA tile 128x128, 4 warps (2m x 2n), warp tile 64x64. KB=16, 2-stage LDG.
// mode 0: fused QKV (z=0 Q, z=1 K, z=2 V), mode 1: output proj -> C_ext
// ===========================================================================
#define GK    1024
#define KB    16
#define NCH   (GK / KB)
#define SST   20

__global__ __launch_bounds__(128, 2) void gemm_tf32_mma(
    const float* __restrict__ seq1, const float* __restrict__ seq2,
    const float* __restrict__ Wq, const float* __restrict__ bq,
    const float* __restrict__ Wk, const float* __restrict__ bk,
    const float* __restrict__ Wv, const float* __restrict__ bv,
    float* __restrict__ C_ext, int mode)
{
    const float* A;
    const float* W;
    const float* bias;
    float* C;
    if (mode == 1) {
        A = (const float*)g_AO; W = Wq; bias = bq; C = C_ext;
    } else {
        const int z = blockIdx.z;
        if (z == 0)      { A = seq1; W = Wq; bias = bq; C = g_Q; }
        else if (z == 1) { A = seq2; W = Wk; bias = bk; C = g_K; }
        else             { A = seq2; W = Wv; bias = bv; C = g_V; }
    }

    __shared__ uint32_t As[2][128 * SST];
    __shared__ uint32_t Bs[2][128 * SST];
    __shared__ float s_bias[128];

    const int tid  = threadIdx.x;
    const int wid  = tid >> 5;
    const int lane = tid & 31;
    const int g    = lane >> 2;
    const int tg   = lane & 3;
    const int mrow = (wid >> 1) * 64;
    const int ncol = (wid & 1) * 64;

    const float* Arow = A + (size_t)blockIdx.y * 128 * GK;
    const float* Wrow = W + (size_t)blockIdx.x * 128 * GK;

    if (tid < 128) s_bias[tid] = bias[blockIdx.x * 128 + tid];

    int rL[4], kL[4];
#pragma unroll
    for (int t = 0; t < 4; t++) {
        const int s = tid + t * 128;
        rL[t] = s >> 2;
        kL[t] = (s & 3) << 2;
    }

    float acc[4][8][4];
#pragma unroll
    for (int mt = 0; mt < 4; mt++)
#pragma unroll
        for (int nt = 0; nt < 8; nt++)
#pragma unroll
            for (int e = 0; e < 4; e++) acc[mt][nt][e] = 0.f;

    {
#pragma unroll
        for (int t = 0; t < 4; t++) {
            float4 va = __ldg((const float4*)(Arow + (size_t)rL[t] * GK + kL[t]));
            float4 vb = __ldg((const float4*)(Wrow + (size_t)rL[t] * GK + kL[t]));
            uint4 u;
            u.x = f2tf32(va.x); u.y = f2tf32(va.y); u.z = f2tf32(va.z); u.w = f2tf32(va.w);
            *(uint4*)&As[0][rL[t] * SST + kL[t]] = u;
            u.x = f2tf32(vb.x); u.y = f2tf32(vb.y); u.z = f2tf32(vb.z); u.w = f2tf32(vb.w);
            *(uint4*)&Bs[0][rL[t] * SST + kL[t]] = u;
        }
    }
    __syncthreads();

    for (int i = 0; i < NCH; i++) {
        const int st = i & 1;
        float4 va[4], vb[4];
        const bool more = (i + 1 < NCH);
        if (more) {
            const int ko = (i + 1) * KB;
#pragma unroll
            for (int t = 0; t < 4; t++) {
                va[t] = __ldg((const float4*)(Arow + (size_t)rL[t] * GK + ko + kL[t]));
                vb[t] = __ldg((const float4*)(Wrow + (size_t)rL[t] * GK + ko + kL[t]));
            }
        }

#pragma unroll
        for (int ks = 0; ks < 2; ks++) {
            uint32_t a[4][4];
#pragma unroll
            for (int mt = 0; mt < 4; mt++) {
                const int rb = mrow + mt * 16 + g;
                a[mt][0] = As[st][(rb)     * SST + ks * 8 + tg];
                a[mt][1] = As[st][(rb + 8) * SST + ks * 8 + tg];
                a[mt][2] = As[st][(rb)     * SST + ks * 8 + tg + 4];
                a[mt][3] = As[st][(rb + 8) * SST + ks * 8 + tg + 4];
            }
#pragma unroll
            for (int nt = 0; nt < 8; nt++) {
                const int rw = ncol + nt * 8 + g;
                uint32_t b0 = Bs[st][rw * SST + ks * 8 + tg];
                uint32_t b1 = Bs[st][rw * SST + ks * 8 + tg + 4];
#pragma unroll
                for (int mt = 0; mt < 4; mt++)
                    mma_tf32(acc[mt][nt][0], acc[mt][nt][1], acc[mt][nt][2], acc[mt][nt][3],
                             a[mt][0], a[mt][1], a[mt][2], a[mt][3], b0, b1);
            }
        }

        if (more) {
            const int ns = st ^ 1;
            uint4 u;
#pragma unroll
            for (int t = 0; t < 4; t++) {
                u.x = f2tf32(va[t].x); u.y = f2tf32(va[t].y);
                u.z = f2tf32(va[t].z); u.w = f2tf32(va[t].w);
                *(uint4*)&As[ns][rL[t] * SST + kL[t]] = u;
                u.x = f2tf32(vb[t].x); u.y = f2tf32(vb[t].y);
                u.z = f2tf32(vb[t].z); u.w = f2tf32(vb[t].w);
                *(uint4*)&Bs[ns][rL[t] * SST + kL[t]] = u;
            }
            __syncthreads();
        }
    }

#pragma unroll
    for (int mt = 0; mt < 4; mt++) {
#pragma unroll
        for (int nt = 0; nt < 8; nt++) {
            const int row = mrow + mt * 16 + g;
            const int col = ncol + nt * 8 + 2 * tg;
            const int gm0 = blockIdx.y * 128 + row;
            const int gc  = blockIdx.x * 128 + col;
            float2 o;
            o.x = acc[mt][nt][0] + s_bias[col];
            o.y = acc[mt][nt][1] + s_bias[col + 1];
            *(float2*)(C + (size_t)gm0 * DIM_ + gc) = o;
            o.x = acc[mt][nt][2] + s_bias[col];
            o.y = acc[mt][nt][3] + s_bias[col + 1];
            *(float2*)(C + (size_t)(gm0 + 8) * DIM_ + gc) = o;
        }
    }
}

// ===========================================================================
// Fused attention v2: separate K/V SMEM buffers, front-loaded LDGs,
// 2 barriers per chunk (was 4). Math order identical to v1.
// ===========================================================================
#define KST 68
#define VST 72

__global__ __launch_bounds__(256) void attn_fused_kernel(
    const float* __restrict__ atc1, const float* __restrict__ atc2,
    const float* __restrict__ U, const float* __restrict__ mixp)
{
    const int bh = blockIdx.y;
    const int b  = bh >> 4;
    const int h  = bh & 15;
    const int i0 = blockIdx.x * 128;

    __shared__ uint32_t Ks[64 * KST];
    __shared__ uint32_t Vs[64 * VST];
    __shared__ float Atc2s[64][5];

    const int tid  = threadIdx.x;
    const int wid  = tid >> 5;
    const int lane = tid & 31;
    const int g    = lane >> 2;
    const int tg   = lane & 3;
    const int wrow = wid * 16;

    // per-thread staging slots (4 per tile)
    int rS[4], cS[4];
#pragma unroll
    for (int t = 0; t < 4; t++) {
        const int s = tid + t * 256;
        rS[t] = s >> 4;
        cS[t] = (s & 15) << 2;
    }

    uint32_t qf[8][4];
    {
        const float* Qb = g_Q + (size_t)(b * L_ + i0 + wrow) * DIM_ + h * HD_;
#pragma unroll
        for (int kb = 0; kb < 8; kb++) {
            qf[kb][0] = f2tf32(__ldg(Qb + (size_t)g       * DIM_ + kb * 8 + tg));
            qf[kb][1] = f2tf32(__ldg(Qb + (size_t)(g + 8) * DIM_ + kb * 8 + tg));
            qf[kb][2] = f2tf32(__ldg(Qb + (size_t)g       * DIM_ + kb * 8 + tg + 4));
            qf[kb][3] = f2tf32(__ldg(Qb + (size_t)(g + 8) * DIM_ + kb * 8 + tg + 4));
        }
    }

    float a1u0[5], a1u8[5];
    {
        const float* a1p = atc1 + (size_t)(b * L_ + i0 + wrow + g) * 5;
        float a1_0[5], a1_8[5];
#pragma unroll
        for (int p = 0; p < 5; p++) {
            a1_0[p] = __ldg(a1p + p);
            a1_8[p] = __ldg(a1p + 40 + p);
        }
#pragma unroll
        for (int q = 0; q < 5; q++) {
            float s0 = 0.f, s8 = 0.f;
#pragma unroll
            for (int p = 0; p < 5; p++) {
                float u = __ldg(&U[h * 25 + p * 5 + q]);
                s0 = fmaf(a1_0[p], u, s0);
                s8 = fmaf(a1_8[p], u, s8);
            }
            a1u0[q] = s0;
            a1u8[q] = s8;
        }
    }

    float m1[2] = {-1e30f, -1e30f}, l1[2] = {0.f, 0.f};
    float m2[2] = {-1e30f, -1e30f}, l2[2] = {0.f, 0.f};
    float O1[8][4], O2[8][4];
#pragma unroll
    for (int nb = 0; nb < 8; nb++)
#pragma unroll
        for (int e = 0; e < 4; e++) { O1[nb][e] = 0.f; O2[nb][e] = 0.f; }

    for (int ch = 0; ch < 8; ch++) {
        const int j0 = ch * 64;

        // ---- front-load all global reads for this chunk (overlaps prev PV)
        float4 kreg[4], vreg[4];
#pragma unroll
        for (int t = 0; t < 4; t++) {
            kreg[t] = *(const float4*)&g_K[(size_t)(b * L_ + j0 + rS[t]) * DIM_ + h * HD_ + cS[t]];
            vreg[t] = *(const float4*)&g_V[(size_t)(b * L_ + j0 + rS[t]) * DIM_ + h * HD_ + cS[t]];
        }
        float a2reg[5];
        if (tid < 64) {
#pragma unroll
            for (int q = 0; q < 5; q++)
                a2reg[q] = __ldg(&atc2[(size_t)(b * L_ + j0 + tid) * 5 + q]);
        }

        __syncthreads();   // previous chunk's QK (Ks) and PV (Vs) reads done

#pragma unroll
        for (int t = 0; t < 4; t++) {
            uint4 u;
            u.x = f2tf32(kreg[t].x); u.y = f2tf32(kreg[t].y);
            u.z = f2tf32(kreg[t].z); u.w = f2tf32(kreg[t].w);
            *(uint4*)&Ks[rS[t] * KST + cS[t]] = u;
            u.x = f2tf32(vreg[t].x); u.y = f2tf32(vreg[t].y);
            u.z = f2tf32(vreg[t].z); u.w = f2tf32(vreg[t].w);
            *(uint4*)&Vs[rS[t] * VST + cS[t]] = u;
        }
        if (tid < 64) {
#pragma unroll
            for (int q = 0; q < 5; q++) Atc2s[tid][q] = a2reg[q];
        }
        __syncthreads();   // K, V, atc2 visible

        // ---- QK mma
        float s1[8][4];
#pragma unroll
        for (int nt = 0; nt < 8; nt++)
#pragma unroll
            for (int e = 0; e < 4; e++) s1[nt][e] = 0.f;
#pragma unroll
        for (int kb = 0; kb < 8; kb++) {
#pragma unroll
            for (int nt = 0; nt < 8; nt++) {
                uint32_t b0 = Ks[(nt * 8 + g) * KST + kb * 8 + tg];
                uint32_t b1 = Ks[(nt * 8 + g) * KST + kb * 8 + tg + 4];
                mma_tf32(s1[nt][0], s1[nt][1], s1[nt][2], s1[nt][3],
                         qf[kb][0], qf[kb][1], qf[kb][2], qf[kb][3], b0, b1);
            }
        }
        // ---- bio scores in fragment layout
        float s2[8][4];
#pragma unroll
        for (int nt = 0; nt < 8; nt++) {
            const int c0 = nt * 8 + 2 * tg;
            float d00 = 0.f, d01 = 0.f, d80 = 0.f, d81 = 0.f;
#pragma unroll
            for (int q = 0; q < 5; q++) {
                float a20 = Atc2s[c0][q];
                float a21 = Atc2s[c0 + 1][q];
                d00 = fmaf(a1u0[q], a20, d00);
                d01 = fmaf(a1u0[q], a21, d01);
                d80 = fmaf(a1u8[q], a20, d80);
                d81 = fmaf(a1u8[q], a21, d81);
            }
            s2[nt][0] = d00; s2[nt][1] = d01; s2[nt][2] = d80; s2[nt][3] = d81;
#pragma unroll
            for (int e = 0; e < 4; e++) s1[nt][e] *= 0.125f;
        }

        // ---- chunk row maxes
        float cm1g = -1e30f, cm1h = -1e30f, cm2g = -1e30f, cm2h = -1e30f;
#pragma unroll
        for (int nt = 0; nt < 8; nt++) {
            cm1g = fmaxf(cm1g, fmaxf(s1[nt][0], s1[nt][1]));
            cm1h = fmaxf(cm1h, fmaxf(s1[nt][2], s1[nt][3]));
            cm2g = fmaxf(cm2g, fmaxf(s2[nt][0], s2[nt][1]));
            cm2h = fmaxf(cm2h, fmaxf(s2[nt][2], s2[nt][3]));
        }
#pragma unroll
        for (int o = 1; o <= 2; o <<= 1) {
            cm1g = fmaxf(cm1g, __shfl_xor_sync(0xffffffffu, cm1g, o));
            cm1h = fmaxf(cm1h, __shfl_xor_sync(0xffffffffu, cm1h, o));
            cm2g = fmaxf(cm2g, __shfl_xor_sync(0xffffffffu, cm2g, o));
            cm2h = fmaxf(cm2h, __shfl_xor_sync(0xffffffffu, cm2h, o));
        }

        // ---- online rescale
        float nm, al;
        nm = fmaxf(m1[0], cm1g); al = __expf(m1[0] - nm); m1[0] = nm; l1[0] *= al;
#pragma unroll
        for (int nb = 0; nb < 8; nb++) { O1[nb][0] *= al; O1[nb][1] *= al; }
        nm = fmaxf(m1[1], cm1h); al = __expf(m1[1] - nm); m1[1] = nm; l1[1] *= al;
#pragma unroll
        for (int nb = 0; nb < 8; nb++) { O1[nb][2] *= al; O1[nb][3] *= al; }
        nm = fmaxf(m2[0], cm2g); al = __expf(m2[0] - nm); m2[0] = nm; l2[0] *= al;
#pragma unroll
        for (int nb = 0; nb < 8; nb++) { O2[nb][0] *= al; O2[nb][1] *= al; }
        nm = fmaxf(m2[1], cm2h); al = __expf(m2[1] - nm); m2[1] = nm; l2[1] *= al;
#pragma unroll
        for (int nb = 0; nb < 8; nb++) { O2[nb][2] *= al; O2[nb][3] *= al; }

        // ---- exp in place + row sums
        float rs1g = 0.f, rs1h = 0.f, rs2g = 0.f, rs2h = 0.f;
#pragma unroll
        for (int nt = 0; nt < 8; nt++) {
            s1[nt][0] = __expf(s1[nt][0] - m1[0]); rs1g += s1[nt][0];
            s1[nt][1] = __expf(s1[nt][1] - m1[0]); rs1g += s1[nt][1];
            s1[nt][2] = __expf(s1[nt][2] - m1[1]); rs1h += s1[nt][2];
            s1[nt][3] = __expf(s1[nt][3] - m1[1]); rs1h += s1[nt][3];
            s2[nt][0] = __expf(s2[nt][0] - m2[0]); rs2g += s2[nt][0];
            s2[nt][1] = __expf(s2[nt][1] - m2[0]); rs2g += s2[nt][1];
            s2[nt][2] = __expf(s2[nt][2] - m2[1]); rs2h += s2[nt][2];
            s2[nt][3] = __expf(s2[nt][3] - m2[1]); rs2h += s2[nt][3];
        }
#pragma unroll
        for (int o = 1; o <= 2; o <<= 1) {
            rs1g += __shfl_xor_sync(0xffffffffu, rs1g, o);
            rs1h += __shfl_xor_sync(0xffffffffu, rs1h, o);
            rs2g += __shfl_xor_sync(0xffffffffu, rs2g, o);
            rs2h += __shfl_xor_sync(0xffffffffu, rs2h, o);
        }
        l1[0] += rs1g; l1[1] += rs1h;
        l2[0] += rs2g; l2[1] += rs2h;

        // ---- PV mma (reads Vs; no barrier needed, Vs already populated)
        const int srcA = (lane & ~3) | (tg >> 1);
        const int srcB = srcA + 2;
        const bool odd = (tg & 1);
#pragma unroll
        for (int kb = 0; kb < 8; kb++) {
            float p0a = __shfl_sync(0xffffffffu, s1[kb][0], srcA);
            float p1a = __shfl_sync(0xffffffffu, s1[kb][1], srcA);
            float p2a = __shfl_sync(0xffffffffu, s1[kb][2], srcA);
            float p3a = __shfl_sync(0xffffffffu, s1[kb][3], srcA);
            float p0b = __shfl_sync(0xffffffffu, s1[kb][0], srcB);
            float p1b = __shfl_sync(0xffffffffu, s1[kb][1], srcB);
            float p2b = __shfl_sync(0xffffffffu, s1[kb][2], srcB);
            float p3b = __shfl_sync(0xffffffffu, s1[kb][3], srcB);
            uint32_t A1_0 = f2tf32(odd ? p1a : p0a);
            uint32_t A1_1 = f2tf32(odd ? p3a : p2a);
            uint32_t A1_2 = f2tf32(odd ? p1b : p0b);
            uint32_t A1_3 = f2tf32(odd ? p3b : p2b);

            p0a = __shfl_sync(0xffffffffu, s2[kb][0], srcA);
            p1a = __shfl_sync(0xffffffffu, s2[kb][1], srcA);
            p2a = __shfl_sync(0xffffffffu, s2[kb][2], srcA);
            p3a = __shfl_sync(0xffffffffu, s2[kb][3], srcA);
            p0b = __shfl_sync(0xffffffffu, s2[kb][0], srcB);
            p1b = __shfl_sync(0xffffffffu, s2[kb][1], srcB);
            p2b = __shfl_sync(0xffffffffu, s2[kb][2], srcB);
            p3b = __shfl_sync(0xffffffffu, s2[kb][3], srcB);
            uint32_t A2_0 = f2tf32(odd ? p1a : p0a);
            uint32_t A2_1 = f2tf32(odd ? p3a : p2a);
            uint32_t A2_2 = f2tf32(odd ? p1b : p0b);
            uint32_t A2_3 = f2tf32(odd ? p3b : p2b);

#pragma unroll
            for (int nb = 0; nb < 8; nb++) {
                uint32_t b0 = Vs[(kb * 8 + tg)     * VST + nb * 8 + g];
                uint32_t b1 = Vs[(kb * 8 + tg + 4) * VST + nb * 8 + g];
                mma_tf32(O1[nb][0], O1[nb][1], O1[nb][2], O1[nb][3],
                         A1_0, A1_1, A1_2, A1_3, b0, b1);
                mma_tf32(O2[nb][0], O2[nb][1], O2[nb][2], O2[nb][3],
                         A2_0, A2_1, A2_2, A2_3, b0, b1);
            }
        }
    }

    // ---- combine + write
    const float mixr = (tanhf(__ldg(mixp)) + 1.f) * 0.5f;
    const float w1g = (1.f - mixr) / l1[0], w1h = (1.f - mixr) / l1[1];
    const float w2g = mixr / l2[0],         w2h = mixr / l2[1];
    float* Ao = g_AO + (size_t)(b * L_ + i0 + wrow) * DIM_ + h * HD_;
#pragma unroll
    for (int nb = 0; nb < 8; nb++) {
        const int col = nb * 8 + 2 * tg;
        float2 o;
        o.x = O1[nb][0] * w1g + O2[nb][0] * w2g;
        o.y = O1[nb][1] * w1g + O2[nb][1] * w2g;
        *(float2*)(Ao + (size_t)g * DIM_ + col) = o;
        o.x = O1[nb][2] * w1h + O2[nb][2] * w2h;
        o.y = O1[nb][3] * w1h + O2[nb][3] * w2h;
        *(float2*)(Ao + (size_t)(g + 8) * DIM_ + col) = o;
    }
}

// ---------------------------------------------------------------------------
extern "C" void kernel_launch(void* const* d_in, const int* in_sizes, int n_in,
                              void* d_out, int out_size)
{
    const float* seq1 = (const float*)d_in[0];
    const float* seq2 = (const float*)d_in[1];
    const float* atc1 = (const float*)d_in[2];
    const float* atc2 = (const float*)d_in[3];
    const float* Wq   = (const float*)d_in[4];
    const float* bq   = (const float*)d_in[5];
    const float* Wk   = (const float*)d_in[6];
    const float* bk   = (const float*)d_in[7];
    const float* Wv   = (const float*)d_in[8];
    const float* bv   = (const float*)d_in[9];
    const float* Wo   = (const float*)d_in[10];
    const float* bo   = (const float*)d_in[11];
    const float* U    = (const float*)d_in[12];
    const float* mixp = (const float*)d_in[13];
    float* out = (float*)d_out;

    const int M = B_ * L_;                       // 4096

    // Fused Q/K/V projections (round-6 GEMM)
    gemm_tf32_mma<<<dim3(DIM_ / 128, M / 128, 3), 128>>>(
        seq1, seq2, Wq, bq, Wk, bk, Wv, bv, nullptr, 0);

    // Fused attention v2 (2 barriers/chunk, front-loaded LDGs)
    attn_fused_kernel<<<dim3(L_ / 128, B_ * H_), 256>>>(atc1, atc2, U, mixp);

    // Output projection -> d_out
    gemm_tf32_mma<<<dim3(DIM_ / 128, M / 128, 1), 128>>>(
        nullptr, nullptr, Wo, bo, nullptr, nullptr, nullptr, nullptr, out, 1);
}

// round 9
// speedup vs baseline: 1.5912x; 1.4250x over previous
#include <cuda_runtime.h>
#include <cuda_fp16.h>
#include <math.h>
#include <cstdint>

#define B_   8
#define H_   16
#define L_   512
#define DIM_ 1024
#define HD_  64

// Scratch (device globals: allocation-free per harness rules)
__device__ __align__(16) float g_Q [B_ * L_ * DIM_];
__device__ __align__(16) float g_K [B_ * L_ * DIM_];
__device__ __align__(16) float g_V [B_ * L_ * DIM_];
__device__ __align__(16) float g_AO[B_ * L_ * DIM_];

// ===========================================================================
// fp16 helpers (baseline PTX, supported on compute_103)
// ===========================================================================
// pack two fp32 -> f16x2 (lo in low half, hi in high half)
__device__ __forceinline__ uint32_t pk(float lo, float hi) {
    uint32_t d;
    asm("cvt.rn.f16x2.f32 %0, %1, %2;" : "=r"(d) : "f"(hi), "f"(lo));
    return d;
}

__device__ __forceinline__ void mma_f16(
    float& d0, float& d1, float& d2, float& d3,
    uint32_t a0, uint32_t a1, uint32_t a2, uint32_t a3,
    uint32_t b0, uint32_t b1)
{
    asm volatile(
        "mma.sync.aligned.m16n8k16.row.col.f32.f16.f16.f32 "
        "{%0,%1,%2,%3}, {%4,%5,%6,%7}, {%8,%9}, {%0,%1,%2,%3};"
        : "+f"(d0), "+f"(d1), "+f"(d2), "+f"(d3)
        : "r"(a0), "r"(a1), "r"(a2), "r"(a3), "r"(b0), "r"(b1));
}

// ===========================================================================
// Projection GEMM (fp16 mma): C[M,1024] = A[M,1024] @ W[1024,1024]^T + bias
// CTA tile 128x128, 4 warps (2m x 2n), warp tile 64x64.
// KB=16 (one m16n8k16 step/chunk), double-buffered, LDG register prefetch.
// SMEM rows: 8 f16x2 words + pad -> SST=12 (frag banks 12g+tg: conflict-free)
// mode 0: fused QKV (z=0 Q, z=1 K, z=2 V), mode 1: output proj -> C_ext
// ===========================================================================
#define GK    1024
#define KB    16
#define NCH   (GK / KB)
#define SST   12

__global__ __launch_bounds__(128, 2) void gemm_f16_mma(
    const float* __restrict__ seq1, const float* __restrict__ seq2,
    const float* __restrict__ Wq, const float* __restrict__ bq,
    const float* __restrict__ Wk, const float* __restrict__ bk,
    const float* __restrict__ Wv, const float* __restrict__ bv,
    float* __restrict__ C_ext, int mode)
{
    const float* A;
    const float* W;
    const float* bias;
    float* C;
    if (mode == 1) {
        A = (const float*)g_AO; W = Wq; bias = bq; C = C_ext;
    } else {
        const int z = blockIdx.z;
        if (z == 0)      { A = seq1; W = Wq; bias = bq; C = g_Q; }
        else if (z == 1) { A = seq2; W = Wk; bias = bk; C = g_K; }
        else             { A = seq2; W = Wv; bias = bv; C = g_V; }
    }

    __shared__ uint32_t As[2][128 * SST];
    __shared__ uint32_t Bs[2][128 * SST];
    __shared__ float s_bias[128];

    const int tid  = threadIdx.x;
    const int wid  = tid >> 5;
    const int lane = tid & 31;
    const int g    = lane >> 2;
    const int tg   = lane & 3;
    const int mrow = (wid >> 1) * 64;
    const int ncol = (wid & 1) * 64;

    const float* Arow = A + (size_t)blockIdx.y * 128 * GK;
    const float* Wrow = W + (size_t)blockIdx.x * 128 * GK;

    if (tid < 128) s_bias[tid] = bias[blockIdx.x * 128 + tid];

    // staging slots: 512 float4 per fp32 tile, 4 per thread
    int rL[4], kL[4];
#pragma unroll
    for (int t = 0; t < 4; t++) {
        const int s = tid + t * 128;
        rL[t] = s >> 2;
        kL[t] = (s & 3) << 2;      // float col {0,4,8,12} -> word col kL>>1
    }

    float acc[4][8][4];
#pragma unroll
    for (int mt = 0; mt < 4; mt++)
#pragma unroll
        for (int nt = 0; nt < 8; nt++)
#pragma unroll
            for (int e = 0; e < 4; e++) acc[mt][nt][e] = 0.f;

    // Prologue: chunk 0 -> stage 0
    {
#pragma unroll
        for (int t = 0; t < 4; t++) {
            float4 va = __ldg((const float4*)(Arow + (size_t)rL[t] * GK + kL[t]));
            float4 vb = __ldg((const float4*)(Wrow + (size_t)rL[t] * GK + kL[t]));
            const int wo = rL[t] * SST + (kL[t] >> 1);
            *(uint2*)&As[0][wo] = make_uint2(pk(va.x, va.y), pk(va.z, va.w));
            *(uint2*)&Bs[0][wo] = make_uint2(pk(vb.x, vb.y), pk(vb.z, vb.w));
        }
    }
    __syncthreads();

    for (int i = 0; i < NCH; i++) {
        const int st = i & 1;
        float4 va[4], vb[4];
        const bool more = (i + 1 < NCH);
        if (more) {
            const int ko = (i + 1) * KB;
#pragma unroll
            for (int t = 0; t < 4; t++) {
                va[t] = __ldg((const float4*)(Arow + (size_t)rL[t] * GK + ko + kL[t]));
                vb[t] = __ldg((const float4*)(Wrow + (size_t)rL[t] * GK + ko + kL[t]));
            }
        }

        // one m16n8k16 k-step per chunk
        {
            uint32_t a[4][4];
#pragma unroll
            for (int mt = 0; mt < 4; mt++) {
                const int rb = mrow + mt * 16 + g;
                a[mt][0] = As[st][(rb)     * SST + tg];
                a[mt][1] = As[st][(rb + 8) * SST + tg];
                a[mt][2] = As[st][(rb)     * SST + tg + 4];
                a[mt][3] = As[st][(rb + 8) * SST + tg + 4];
            }
#pragma unroll
            for (int nt = 0; nt < 8; nt++) {
                const int rw = ncol + nt * 8 + g;
                uint32_t b0 = Bs[st][rw * SST + tg];
                uint32_t b1 = Bs[st][rw * SST + tg + 4];
#pragma unroll
                for (int mt = 0; mt < 4; mt++)
                    mma_f16(acc[mt][nt][0], acc[mt][nt][1], acc[mt][nt][2], acc[mt][nt][3],
                            a[mt][0], a[mt][1], a[mt][2], a[mt][3], b0, b1);
            }
        }

        if (more) {
            const int ns = st ^ 1;
#pragma unroll
            for (int t = 0; t < 4; t++) {
                const int wo = rL[t] * SST + (kL[t] >> 1);
                *(uint2*)&As[ns][wo] = make_uint2(pk(va[t].x, va[t].y), pk(va[t].z, va[t].w));
                *(uint2*)&Bs[ns][wo] = make_uint2(pk(vb[t].x, vb[t].y), pk(vb[t].z, vb[t].w));
            }
            __syncthreads();
        }
    }

#pragma unroll
    for (int mt = 0; mt < 4; mt++) {
#pragma unroll
        for (int nt = 0; nt < 8; nt++) {
            const int row = mrow + mt * 16 + g;
            const int col = ncol + nt * 8 + 2 * tg;
            const int gm0 = blockIdx.y * 128 + row;
            const int gc  = blockIdx.x * 128 + col;
            float2 o;
            o.x = acc[mt][nt][0] + s_bias[col];
            o.y = acc[mt][nt][1] + s_bias[col + 1];
            *(float2*)(C + (size_t)gm0 * DIM_ + gc) = o;
            o.x = acc[mt][nt][2] + s_bias[col];
            o.y = acc[mt][nt][3] + s_bias[col + 1];
            *(float2*)(C + (size_t)(gm0 + 8) * DIM_ + gc) = o;
        }
    }
}

// ===========================================================================
// Fused attention (fp16 mma): QK^T -> dual online softmax (+Atchley bias)
// -> mix -> @V. K tile [j][d] f16x2 words (KST=36); V tile packed j-pairs
// Vw[jp][d] (VST=72). P fragments pack directly from QK C-regs (no shuffles).
// ===========================================================================
#define KST 36
#define VST 72

__global__ __launch_bounds__(256) void attn_fused_kernel(
    const float* __restrict__ atc1, const float* __restrict__ atc2,
    const float* __restrict__ U, const float* __restrict__ mixp)
{
    const int bh = blockIdx.y;
    const int b  = bh >> 4;
    const int h  = bh & 15;
    const int i0 = blockIdx.x * 128;

    __shared__ uint32_t Ks[64 * KST];   // 64 rows x 32 words
    __shared__ uint32_t Vw[32 * VST];   // 32 jp-rows x 64 words
    __shared__ float Atc2s[64][5];

    const int tid  = threadIdx.x;
    const int wid  = tid >> 5;
    const int lane = tid & 31;
    const int g    = lane >> 2;
    const int tg   = lane & 3;
    const int wrow = wid * 16;

    // K staging slots: 1024 float4, 4/thread
    int rK[4], cK[4];
#pragma unroll
    for (int t = 0; t < 4; t++) {
        const int s = tid + t * 256;
        rK[t] = s >> 4;
        cK[t] = (s & 15) << 2;
    }
    // V staging slots: 512 (jp, dquad) pairs, 2/thread
    int jV[2], dV[2];
#pragma unroll
    for (int t = 0; t < 2; t++) {
        const int s = tid + t * 256;
        jV[t] = s >> 4;
        dV[t] = (s & 15) << 2;
    }

    // Q fragments (fp16): 4 k16 blocks
    uint32_t qf[4][4];
    {
        const float* Qb = g_Q + (size_t)(b * L_ + i0 + wrow) * DIM_ + h * HD_;
#pragma unroll
        for (int kb = 0; kb < 4; kb++) {
            float2 q00 = *(const float2*)(Qb + (size_t)g       * DIM_ + 16 * kb + 2 * tg);
            float2 q80 = *(const float2*)(Qb + (size_t)(g + 8) * DIM_ + 16 * kb + 2 * tg);
            float2 q01 = *(const float2*)(Qb + (size_t)g       * DIM_ + 16 * kb + 2 * tg + 8);
            float2 q81 = *(const float2*)(Qb + (size_t)(g + 8) * DIM_ + 16 * kb + 2 * tg + 8);
            qf[kb][0] = pk(q00.x, q00.y);
            qf[kb][1] = pk(q80.x, q80.y);
            qf[kb][2] = pk(q01.x, q01.y);
            qf[kb][3] = pk(q81.x, q81.y);
        }
    }

    float a1u0[5], a1u8[5];
    {
        const float* a1p = atc1 + (size_t)(b * L_ + i0 + wrow + g) * 5;
        float a1_0[5], a1_8[5];
#pragma unroll
        for (int p = 0; p < 5; p++) {
            a1_0[p] = __ldg(a1p + p);
            a1_8[p] = __ldg(a1p + 40 + p);
        }
#pragma unroll
        for (int q = 0; q < 5; q++) {
            float s0 = 0.f, s8 = 0.f;
#pragma unroll
            for (int p = 0; p < 5; p++) {
                float u = __ldg(&U[h * 25 + p * 5 + q]);
                s0 = fmaf(a1_0[p], u, s0);
                s8 = fmaf(a1_8[p], u, s8);
            }
            a1u0[q] = s0;
            a1u8[q] = s8;
        }
    }

    float m1[2] = {-1e30f, -1e30f}, l1[2] = {0.f, 0.f};
    float m2[2] = {-1e30f, -1e30f}, l2[2] = {0.f, 0.f};
    float O1[8][4], O2[8][4];
#pragma unroll
    for (int nb = 0; nb < 8; nb++)
#pragma unroll
        for (int e = 0; e < 4; e++) { O1[nb][e] = 0.f; O2[nb][e] = 0.f; }

    for (int ch = 0; ch < 8; ch++) {
        const int j0 = ch * 64;

        // ---- front-load global reads (overlaps previous chunk's PV)
        float4 kreg[4];
#pragma unroll
        for (int t = 0; t < 4; t++)
            kreg[t] = *(const float4*)&g_K[(size_t)(b * L_ + j0 + rK[t]) * DIM_ + h * HD_ + cK[t]];
        float4 vregE[2], vregO[2];
#pragma unroll
        for (int t = 0; t < 2; t++) {
            vregE[t] = *(const float4*)&g_V[(size_t)(b * L_ + j0 + 2 * jV[t])     * DIM_ + h * HD_ + dV[t]];
            vregO[t] = *(const float4*)&g_V[(size_t)(b * L_ + j0 + 2 * jV[t] + 1) * DIM_ + h * HD_ + dV[t]];
        }
        float a2reg[5];
        if (tid < 64) {
#pragma unroll
            for (int q = 0; q < 5; q++)
                a2reg[q] = __ldg(&atc2[(size_t)(b * L_ + j0 + tid) * 5 + q]);
        }

        __syncthreads();   // previous chunk's Ks/Vw reads complete

#pragma unroll
        for (int t = 0; t < 4; t++) {
            *(uint2*)&Ks[rK[t] * KST + (cK[t] >> 1)] =
                make_uint2(pk(kreg[t].x, kreg[t].y), pk(kreg[t].z, kreg[t].w));
        }
#pragma unroll
        for (int t = 0; t < 2; t++) {
            uint4 u;
            u.x = pk(vregE[t].x, vregO[t].x);
            u.y = pk(vregE[t].y, vregO[t].y);
            u.z = pk(vregE[t].z, vregO[t].z);
            u.w = pk(vregE[t].w, vregO[t].w);
            *(uint4*)&Vw[jV[t] * VST + dV[t]] = u;
        }
        if (tid < 64) {
#pragma unroll
            for (int q = 0; q < 5; q++) Atc2s[tid][q] = a2reg[q];
        }
        __syncthreads();   // K, V, atc2 visible

        // ---- QK mma (fp16, 4 k16 steps)
        float s1[8][4];
#pragma unroll
        for (int nt = 0; nt < 8; nt++)
#pragma unroll
            for (int e = 0; e < 4; e++) s1[nt][e] = 0.f;
#pragma unroll
        for (int kb = 0; kb < 4; kb++) {
#pragma unroll
            for (int nt = 0; nt < 8; nt++) {
                uint32_t b0 = Ks[(nt * 8 + g) * KST + 8 * kb + tg];
                uint32_t b1 = Ks[(nt * 8 + g) * KST + 8 * kb + tg + 4];
                mma_f16(s1[nt][0], s1[nt][1], s1[nt][2], s1[nt][3],
                        qf[kb][0], qf[kb][1], qf[kb][2], qf[kb][3], b0, b1);
            }
        }

        // ---- bio scores in fragment layout (fp32)
        float s2[8][4];
#pragma unroll
        for (int nt = 0; nt < 8; nt++) {
            const int c0 = nt * 8 + 2 * tg;
            float d00 = 0.f, d01 = 0.f, d80 = 0.f, d81 = 0.f;
#pragma unroll
            for (int q = 0; q < 5; q++) {
                float a20 = Atc2s[c0][q];
                float a21 = Atc2s[c0 + 1][q];
                d00 = fmaf(a1u0[q], a20, d00);
                d01 = fmaf(a1u0[q], a21, d01);
                d80 = fmaf(a1u8[q], a20, d80);
                d81 = fmaf(a1u8[q], a21, d81);
            }
            s2[nt][0] = d00; s2[nt][1] = d01; s2[nt][2] = d80; s2[nt][3] = d81;
#pragma unroll
            for (int e = 0; e < 4; e++) s1[nt][e] *= 0.125f;
        }

        // ---- chunk row maxes
        float cm1g = -1e30f, cm1h = -1e30f, cm2g = -1e30f, cm2h = -1e30f;
#pragma unroll
        for (int nt = 0; nt < 8; nt++) {
            cm1g = fmaxf(cm1g, fmaxf(s1[nt][0], s1[nt][1]));
            cm1h = fmaxf(cm1h, fmaxf(s1[nt][2], s1[nt][3]));
            cm2g = fmaxf(cm2g, fmaxf(s2[nt][0], s2[nt][1]));
            cm2h = fmaxf(cm2h, fmaxf(s2[nt][2], s2[nt][3]));
        }
#pragma unroll
        for (int o = 1; o <= 2; o <<= 1) {
            cm1g = fmaxf(cm1g, __shfl_xor_sync(0xffffffffu, cm1g, o));
            cm1h = fmaxf(cm1h, __shfl_xor_sync(0xffffffffu, cm1h, o));
            cm2g = fmaxf(cm2g, __shfl_xor_sync(0xffffffffu, cm2g, o));
            cm2h = fmaxf(cm2h, __shfl_xor_sync(0xffffffffu, cm2h, o));
        }

        // ---- online rescale
        float nm, al;
        nm = fmaxf(m1[0], cm1g); al = __expf(m1[0] - nm); m1[0] = nm; l1[0] *= al;
#pragma unroll
        for (int nb = 0; nb < 8; nb++) { O1[nb][0] *= al; O1[nb][1] *= al; }
        nm = fmaxf(m1[1], cm1h); al = __expf(m1[1] - nm); m1[1] = nm; l1[1] *= al;
#pragma unroll
        for (int nb = 0; nb < 8; nb++) { O1[nb][2] *= al; O1[nb][3] *= al; }
        nm = fmaxf(m2[0], cm2g); al = __expf(m2[0] - nm); m2[0] = nm; l2[0] *= al;
#pragma unroll
        for (int nb = 0; nb < 8; nb++) { O2[nb][0] *= al; O2[nb][1] *= al; }
        nm = fmaxf(m2[1], cm2h); al = __expf(m2[1] - nm); m2[1] = nm; l2[1] *= al;
#pragma unroll
        for (int nb = 0; nb < 8; nb++) { O2[nb][2] *= al; O2[nb][3] *= al; }

        // ---- exp in place + row sums
        float rs1g = 0.f, rs1h = 0.f, rs2g = 0.f, rs2h = 0.f;
#pragma unroll
        for (int nt = 0; nt < 8; nt++) {
            s1[nt][0] = __expf(s1[nt][0] - m1[0]); rs1g += s1[nt][0];
            s1[nt][1] = __expf(s1[nt][1] - m1[0]); rs1g += s1[nt][1];
            s1[nt][2] = __expf(s1[nt][2] - m1[1]); rs1h += s1[nt][2];
            s1[nt][3] = __expf(s1[nt][3] - m1[1]); rs1h += s1[nt][3];
            s2[nt][0] = __expf(s2[nt][0] - m2[0]); rs2g += s2[nt][0];
            s2[nt][1] = __expf(s2[nt][1] - m2[0]); rs2g += s2[nt][1];
            s2[nt][2] = __expf(s2[nt][2] - m2[1]); rs2h += s2[nt][2];
            s2[nt][3] = __expf(s2[nt][3] - m2[1]); rs2h += s2[nt][3];
        }
#pragma unroll
        for (int o = 1; o <= 2; o <<= 1) {
            rs1g += __shfl_xor_sync(0xffffffffu, rs1g, o);
            rs1h += __shfl_xor_sync(0xffffffffu, rs1h, o);
            rs2g += __shfl_xor_sync(0xffffffffu, rs2g, o);
            rs2h += __shfl_xor_sync(0xffffffffu, rs2h, o);
        }
        l1[0] += rs1g; l1[1] += rs1h;
        l2[0] += rs2g; l2[1] += rs2h;

        // ---- PV mma: A frags pack directly from C-layout (no shuffles)
#pragma unroll
        for (int kb = 0; kb < 4; kb++) {
            uint32_t A1_0 = pk(s1[2 * kb][0],     s1[2 * kb][1]);
            uint32_t A1_1 = pk(s1[2 * kb][2],     s1[2 * kb][3]);
            uint32_t A1_2 = pk(s1[2 * kb + 1][0], s1[2 * kb + 1][1]);
            uint32_t A1_3 = pk(s1[2 * kb + 1][2], s1[2 * kb + 1][3]);
            uint32_t A2_0 = pk(s2[2 * kb][0],     s2[2 * kb][1]);
            uint32_t A2_1 = pk(s2[2 * kb][2],     s2[2 * kb][3]);
            uint32_t A2_2 = pk(s2[2 * kb + 1][0], s2[2 * kb + 1][1]);
            uint32_t A2_3 = pk(s2[2 * kb + 1][2], s2[2 * kb + 1][3]);

#pragma unroll
            for (int nb = 0; nb < 8; nb++) {
                uint32_t b0 = Vw[(8 * kb + tg)     * VST + nb * 8 + g];
                uint32_t b1 = Vw[(8 * kb + tg + 4) * VST + nb * 8 + g];
                mma_f16(O1[nb][0], O1[nb][1], O1[nb][2], O1[nb][3],
                        A1_0, A1_1, A1_2, A1_3, b0, b1);
                mma_f16(O2[nb][0], O2[nb][1], O2[nb][2], O2[nb][3],
                        A2_0, A2_1, A2_2, A2_3, b0, b1);
            }
        }
    }

    // ---- combine + write
    const float mixr = (tanhf(__ldg(mixp)) + 1.f) * 0.5f;
    const float w1g = (1.f - mixr) / l1[0], w1h = (1.f - mixr) / l1[1];
    const float w2g = mixr / l2[0],         w2h = mixr / l2[1];
    float* Ao = g_AO + (size_t)(b * L_ + i0 + wrow) * DIM_ + h * HD_;
#pragma unroll
    for (int nb = 0; nb < 8; nb++) {
        const int col = nb * 8 + 2 * tg;
        float2 o;
        o.x = O1[nb][0] * w1g + O2[nb][0] * w2g;
        o.y = O1[nb][1] * w1g + O2[nb][1] * w2g;
        *(float2*)(Ao + (size_t)g * DIM_ + col) = o;
        o.x = O1[nb][2] * w1h + O2[nb][2] * w2h;
        o.y = O1[nb][3] * w1h + O2[nb][3] * w2h;
        *(float2*)(Ao + (size_t)(g + 8) * DIM_ + col) = o;
    }
}

// ---------------------------------------------------------------------------
extern "C" void kernel_launch(void* const* d_in, const int* in_sizes, int n_in,
                              void* d_out, int out_size)
{
    const float* seq1 = (const float*)d_in[0];
    const float* seq2 = (const float*)d_in[1];
    const float* atc1 = (const float*)d_in[2];
    const float* atc2 = (const float*)d_in[3];
    const float* Wq   = (const float*)d_in[4];
    const float* bq   = (const float*)d_in[5];
    const float* Wk   = (const float*)d_in[6];
    const float* bk   = (const float*)d_in[7];
    const float* Wv   = (const float*)d_in[8];
    const float* bv   = (const float*)d_in[9];
    const float* Wo   = (const float*)d_in[10];
    const float* bo   = (const float*)d_in[11];
    const float* U    = (const float*)d_in[12];
    const float* mixp = (const float*)d_in[13];
    float* out = (float*)d_out;

    const int M = B_ * L_;                       // 4096

    // Fused Q/K/V projections (fp16 mma)
    gemm_f16_mma<<<dim3(DIM_ / 128, M / 128, 3), 128>>>(
        seq1, seq2, Wq, bq, Wk, bk, Wv, bv, nullptr, 0);

    // Fused attention (fp16 mma, shuffle-free P repack)
    attn_fused_kernel<<<dim3(L_ / 128, B_ * H_), 256>>>(atc1, atc2, U, mixp);

    // Output projection -> d_out
    gemm_f16_mma<<<dim3(DIM_ / 128, M / 128, 1), 128>>>(
        nullptr, nullptr, Wo, bo, nullptr, nullptr, nullptr, nullptr, out, 1);
}

// round 10
// speedup vs baseline: 1.8611x; 1.1696x over previous
#include <cuda_runtime.h>
#include <cuda_fp16.h>
#include <math.h>
#include <cstdint>

#define B_   8
#define H_   16
#define L_   512
#define DIM_ 1024
#define HD_  64
#define SEQN (B_ * L_ * DIM_)   // 4194304

// fp16 scratch (device globals: allocation-free per harness rules)
__device__ __align__(16) __half g_Wh [4 * 1024 * 1024];   // Wq,Wk,Wv,Wo
__device__ __align__(16) __half g_s1h[SEQN];
__device__ __align__(16) __half g_s2h[SEQN];
__device__ __align__(16) __half g_Qh [SEQN];
__device__ __align__(16) __half g_Kh [SEQN];
__device__ __align__(16) __half g_Vh [SEQN];
__device__ __align__(16) __half g_AOh[SEQN];

// ===========================================================================
// helpers
// ===========================================================================
__device__ __forceinline__ uint32_t pk(float lo, float hi) {
    uint32_t d;
    asm("cvt.rn.f16x2.f32 %0, %1, %2;" : "=r"(d) : "f"(hi), "f"(lo));
    return d;
}

__device__ __forceinline__ void mma_f16(
    float& d0, float& d1, float& d2, float& d3,
    uint32_t a0, uint32_t a1, uint32_t a2, uint32_t a3,
    uint32_t b0, uint32_t b1)
{
    asm volatile(
        "mma.sync.aligned.m16n8k16.row.col.f32.f16.f16.f32 "
        "{%0,%1,%2,%3}, {%4,%5,%6,%7}, {%8,%9}, {%0,%1,%2,%3};"
        : "+f"(d0), "+f"(d1), "+f"(d2), "+f"(d3)
        : "r"(a0), "r"(a1), "r"(a2), "r"(a3), "r"(b0), "r"(b1));
}

// ===========================================================================
// One-time fp32 -> fp16 conversion of inputs (z selects tensor)
// ===========================================================================
__global__ __launch_bounds__(256) void cvt_f16_kernel(
    const float* __restrict__ s1, const float* __restrict__ s2,
    const float* __restrict__ wq, const float* __restrict__ wk,
    const float* __restrict__ wv, const float* __restrict__ wo)
{
    const int z = blockIdx.z;
    const float* src;
    __half* dst;
    int n4;
    if      (z == 0) { src = s1; dst = g_s1h;               n4 = SEQN / 4; }
    else if (z == 1) { src = s2; dst = g_s2h;               n4 = SEQN / 4; }
    else if (z == 2) { src = wq; dst = g_Wh;                n4 = 262144; }
    else if (z == 3) { src = wk; dst = g_Wh + 1048576;      n4 = 262144; }
    else if (z == 4) { src = wv; dst = g_Wh + 2 * 1048576;  n4 = 262144; }
    else             { src = wo; dst = g_Wh + 3 * 1048576;  n4 = 262144; }

    for (int i = blockIdx.x * blockDim.x + threadIdx.x; i < n4;
         i += gridDim.x * blockDim.x) {
        float4 v = __ldg((const float4*)src + i);
        uint2 o;
        o.x = pk(v.x, v.y);
        o.y = pk(v.z, v.w);
        *((uint2*)dst + i) = o;
    }
}

// ===========================================================================
// fp16-native GEMM: C[M,1024] = A[M,1024] @ W[1024,1024]^T + bias
// CTA tile 128x128, 4 warps (2m x 2n), warp tile 64x64.
// KB=32 halves per chunk (2 m16n8k16 k-steps), double-buffered, reg prefetch.
// mode 0: fused QKV (z selects, fp16 out), mode 1: O-proj (fp32 out)
// ===========================================================================
#define GK    1024
#define KB    32
#define NCH   (GK / KB)   // 32
#define SST   20          // words/row (16 data + 4 pad); frags conflict-free

__global__ __launch_bounds__(128, 2) void gemm_f16(
    const float* __restrict__ bq, const float* __restrict__ bk,
    const float* __restrict__ bv, float* __restrict__ C_ext, int mode)
{
    const __half* A;
    const __half* W;
    const float* bias;
    __half* Ch = nullptr;
    float* Cf = nullptr;
    if (mode == 1) {
        A = g_AOh; W = g_Wh + 3 * 1048576; bias = bq; Cf = C_ext;
    } else {
        const int z = blockIdx.z;
        if (z == 0)      { A = g_s1h; W = g_Wh;               bias = bq; Ch = g_Qh; }
        else if (z == 1) { A = g_s2h; W = g_Wh + 1048576;     bias = bk; Ch = g_Kh; }
        else             { A = g_s2h; W = g_Wh + 2 * 1048576; bias = bv; Ch = g_Vh; }
    }

    __shared__ uint32_t As[2][128 * SST];
    __shared__ uint32_t Bs[2][128 * SST];
    __shared__ float s_bias[128];

    const int tid  = threadIdx.x;
    const int wid  = tid >> 5;
    const int lane = tid & 31;
    const int g    = lane >> 2;
    const int tg   = lane & 3;
    const int mrow = (wid >> 1) * 64;
    const int ncol = (wid & 1) * 64;

    const __half* Arow = A + (size_t)blockIdx.y * 128 * GK;
    const __half* Wrow = W + (size_t)blockIdx.x * 128 * GK;

    if (tid < 128) s_bias[tid] = bias[blockIdx.x * 128 + tid];

    // staging: 128 rows x 4 uint4 per tile per chunk; 4 slots/thread
    int rL[4], qL[4];
#pragma unroll
    for (int t = 0; t < 4; t++) {
        const int s = tid + t * 128;
        rL[t] = s >> 2;
        qL[t] = s & 3;
    }

    float acc[4][8][4];
#pragma unroll
    for (int mt = 0; mt < 4; mt++)
#pragma unroll
        for (int nt = 0; nt < 8; nt++)
#pragma unroll
            for (int e = 0; e < 4; e++) acc[mt][nt][e] = 0.f;

    // Prologue: chunk 0 -> stage 0 (direct fp16 copy, no cvt)
#pragma unroll
    for (int t = 0; t < 4; t++) {
        uint4 a = *(const uint4*)(Arow + (size_t)rL[t] * GK + qL[t] * 8);
        uint4 b = *(const uint4*)(Wrow + (size_t)rL[t] * GK + qL[t] * 8);
        *(uint4*)&As[0][rL[t] * SST + qL[t] * 4] = a;
        *(uint4*)&Bs[0][rL[t] * SST + qL[t] * 4] = b;
    }
    __syncthreads();

    for (int i = 0; i < NCH; i++) {
        const int st = i & 1;
        uint4 va[4], vb[4];
        const bool more = (i + 1 < NCH);
        if (more) {
            const int ko = (i + 1) * KB;
#pragma unroll
            for (int t = 0; t < 4; t++) {
                va[t] = *(const uint4*)(Arow + (size_t)rL[t] * GK + ko + qL[t] * 8);
                vb[t] = *(const uint4*)(Wrow + (size_t)rL[t] * GK + ko + qL[t] * 8);
            }
        }

#pragma unroll
        for (int ks = 0; ks < 2; ks++) {
            uint32_t a[4][4];
#pragma unroll
            for (int mt = 0; mt < 4; mt++) {
                const int rb = mrow + mt * 16 + g;
                a[mt][0] = As[st][(rb)     * SST + ks * 8 + tg];
                a[mt][1] = As[st][(rb + 8) * SST + ks * 8 + tg];
                a[mt][2] = As[st][(rb)     * SST + ks * 8 + tg + 4];
                a[mt][3] = As[st][(rb + 8) * SST + ks * 8 + tg + 4];
            }
#pragma unroll
            for (int nt = 0; nt < 8; nt++) {
                const int rw = ncol + nt * 8 + g;
                uint32_t b0 = Bs[st][rw * SST + ks * 8 + tg];
                uint32_t b1 = Bs[st][rw * SST + ks * 8 + tg + 4];
#pragma unroll
                for (int mt = 0; mt < 4; mt++)
                    mma_f16(acc[mt][nt][0], acc[mt][nt][1], acc[mt][nt][2], acc[mt][nt][3],
                            a[mt][0], a[mt][1], a[mt][2], a[mt][3], b0, b1);
            }
        }

        if (more) {
            const int ns = st ^ 1;
#pragma unroll
            for (int t = 0; t < 4; t++) {
                *(uint4*)&As[ns][rL[t] * SST + qL[t] * 4] = va[t];
                *(uint4*)&Bs[ns][rL[t] * SST + qL[t] * 4] = vb[t];
            }
            __syncthreads();
        }
    }

    // Epilogue
    if (mode == 1) {
#pragma unroll
        for (int mt = 0; mt < 4; mt++) {
#pragma unroll
            for (int nt = 0; nt < 8; nt++) {
                const int row = mrow + mt * 16 + g;
                const int col = ncol + nt * 8 + 2 * tg;
                const int gm0 = blockIdx.y * 128 + row;
                const int gc  = blockIdx.x * 128 + col;
                float2 o;
                o.x = acc[mt][nt][0] + s_bias[col];
                o.y = acc[mt][nt][1] + s_bias[col + 1];
                *(float2*)(Cf + (size_t)gm0 * DIM_ + gc) = o;
                o.x = acc[mt][nt][2] + s_bias[col];
                o.y = acc[mt][nt][3] + s_bias[col + 1];
                *(float2*)(Cf + (size_t)(gm0 + 8) * DIM_ + gc) = o;
            }
        }
    } else {
#pragma unroll
        for (int mt = 0; mt < 4; mt++) {
#pragma unroll
            for (int nt = 0; nt < 8; nt++) {
                const int row = mrow + mt * 16 + g;
                const int col = ncol + nt * 8 + 2 * tg;
                const int gm0 = blockIdx.y * 128 + row;
                const int gc  = blockIdx.x * 128 + col;
                *(uint32_t*)(Ch + (size_t)gm0 * DIM_ + gc) =
                    pk(acc[mt][nt][0] + s_bias[col], acc[mt][nt][1] + s_bias[col + 1]);
                *(uint32_t*)(Ch + (size_t)(gm0 + 8) * DIM_ + gc) =
                    pk(acc[mt][nt][2] + s_bias[col], acc[mt][nt][3] + s_bias[col + 1]);
            }
        }
    }
}

// ===========================================================================
// Fused attention (fp16-native inputs): QK^T -> dual online softmax
// (+Atchley bias) -> mix -> @V. Output -> g_AOh (fp16).
// ===========================================================================
#define KST 36
#define VST 72

__global__ __launch_bounds__(256) void attn_fused_kernel(
    const float* __restrict__ atc1, const float* __restrict__ atc2,
    const float* __restrict__ U, const float* __restrict__ mixp)
{
    const int bh = blockIdx.y;
    const int b  = bh >> 4;
    const int h  = bh & 15;
    const int i0 = blockIdx.x * 128;

    __shared__ uint32_t Ks[64 * KST];   // 64 rows x 32 words
    __shared__ uint32_t Vw[32 * VST];   // 32 jp-rows x 64 words (j-pair packed)
    __shared__ float Atc2s[64][5];

    const int tid  = threadIdx.x;
    const int wid  = tid >> 5;
    const int lane = tid & 31;
    const int g    = lane >> 2;
    const int tg   = tid & 3;
    const int wrow = wid * 16;

    // K staging slots: 512 uint4, 2/thread
    int rK[2], cK[2];
#pragma unroll
    for (int t = 0; t < 2; t++) {
        const int s = tid + t * 256;
        rK[t] = s >> 3;
        cK[t] = s & 7;
    }
    // V merge unit: 1/thread
    const int jV = tid >> 3;
    const int dV = tid & 7;

    // Q fragments: direct word loads from fp16 Q
    uint32_t qf[4][4];
    {
        const uint32_t* Qb = (const uint32_t*)(g_Qh + (size_t)(b * L_ + i0 + wrow) * DIM_ + h * HD_);
#pragma unroll
        for (int kb = 0; kb < 4; kb++) {
            qf[kb][0] = Qb[(size_t)g       * (DIM_ / 2) + 8 * kb + tg];
            qf[kb][1] = Qb[(size_t)(g + 8) * (DIM_ / 2) + 8 * kb + tg];
            qf[kb][2] = Qb[(size_t)g       * (DIM_ / 2) + 8 * kb + tg + 4];
            qf[kb][3] = Qb[(size_t)(g + 8) * (DIM_ / 2) + 8 * kb + tg + 4];
        }
    }

    float a1u0[5], a1u8[5];
    {
        const float* a1p = atc1 + (size_t)(b * L_ + i0 + wrow + g) * 5;
        float a1_0[5], a1_8[5];
#pragma unroll
        for (int p = 0; p < 5; p++) {
            a1_0[p] = __ldg(a1p + p);
            a1_8[p] = __ldg(a1p + 40 + p);
        }
#pragma unroll
        for (int q = 0; q < 5; q++) {
            float s0 = 0.f, s8 = 0.f;
#pragma unroll
            for (int p = 0; p < 5; p++) {
                float u = __ldg(&U[h * 25 + p * 5 + q]);
                s0 = fmaf(a1_0[p], u, s0);
                s8 = fmaf(a1_8[p], u, s8);
            }
            a1u0[q] = s0;
            a1u8[q] = s8;
        }
    }

    float m1[2] = {-1e30f, -1e30f}, l1[2] = {0.f, 0.f};
    float m2[2] = {-1e30f, -1e30f}, l2[2] = {0.f, 0.f};
    float O1[8][4], O2[8][4];
#pragma unroll
    for (int nb = 0; nb < 8; nb++)
#pragma unroll
        for (int e = 0; e < 4; e++) { O1[nb][e] = 0.f; O2[nb][e] = 0.f; }

    for (int ch = 0; ch < 8; ch++) {
        const int j0 = ch * 64;

        // ---- front-load global reads (overlaps previous chunk's PV)
        uint4 kq[2];
#pragma unroll
        for (int t = 0; t < 2; t++)
            kq[t] = *(const uint4*)(g_Kh + (size_t)(b * L_ + j0 + rK[t]) * DIM_ + h * HD_ + cK[t] * 8);
        uint4 ve = *(const uint4*)(g_Vh + (size_t)(b * L_ + j0 + 2 * jV)     * DIM_ + h * HD_ + dV * 8);
        uint4 vo = *(const uint4*)(g_Vh + (size_t)(b * L_ + j0 + 2 * jV + 1) * DIM_ + h * HD_ + dV * 8);
        float a2reg[5];
        if (tid < 64) {
#pragma unroll
            for (int q = 0; q < 5; q++)
                a2reg[q] = __ldg(&atc2[(size_t)(b * L_ + j0 + tid) * 5 + q]);
        }

        __syncthreads();   // previous chunk's Ks/Vw reads complete

#pragma unroll
        for (int t = 0; t < 2; t++)
            *(uint4*)&Ks[rK[t] * KST + cK[t] * 4] = kq[t];
        {
            uint4 o0, o1;
            o0.x = __byte_perm(ve.x, vo.x, 0x5410);
            o0.y = __byte_perm(ve.x, vo.x, 0x7632);
            o0.z = __byte_perm(ve.y, vo.y, 0x5410);
            o0.w = __byte_perm(ve.y, vo.y, 0x7632);
            o1.x = __byte_perm(ve.z, vo.z, 0x5410);
            o1.y = __byte_perm(ve.z, vo.z, 0x7632);
            o1.z = __byte_perm(ve.w, vo.w, 0x5410);
            o1.w = __byte_perm(ve.w, vo.w, 0x7632);
            *(uint4*)&Vw[jV * VST + dV * 8]     = o0;
            *(uint4*)&Vw[jV * VST + dV * 8 + 4] = o1;
        }
        if (tid < 64) {
#pragma unroll
            for (int q = 0; q < 5; q++) Atc2s[tid][q] = a2reg[q];
        }
        __syncthreads();   // K, V, atc2 visible

        // ---- QK mma (4 k16 steps)
        float s1[8][4];
#pragma unroll
        for (int nt = 0; nt < 8; nt++)
#pragma unroll
            for (int e = 0; e < 4; e++) s1[nt][e] = 0.f;
#pragma unroll
        for (int kb = 0; kb < 4; kb++) {
#pragma unroll
            for (int nt = 0; nt < 8; nt++) {
                uint32_t b0 = Ks[(nt * 8 + g) * KST + 8 * kb + tg];
                uint32_t b1 = Ks[(nt * 8 + g) * KST + 8 * kb + tg + 4];
                mma_f16(s1[nt][0], s1[nt][1], s1[nt][2], s1[nt][3],
                        qf[kb][0], qf[kb][1], qf[kb][2], qf[kb][3], b0, b1);
            }
        }

        // ---- bio scores (fp32)
        float s2[8][4];
#pragma unroll
        for (int nt = 0; nt < 8; nt++) {
            const int c0 = nt * 8 + 2 * tg;
            float d00 = 0.f, d01 = 0.f, d80 = 0.f, d81 = 0.f;
#pragma unroll
            for (int q = 0; q < 5; q++) {
                float a20 = Atc2s[c0][q];
                float a21 = Atc2s[c0 + 1][q];
                d00 = fmaf(a1u0[q], a20, d00);
                d01 = fmaf(a1u0[q], a21, d01);
                d80 = fmaf(a1u8[q], a20, d80);
                d81 = fmaf(a1u8[q], a21, d81);
            }
            s2[nt][0] = d00; s2[nt][1] = d01; s2[nt][2] = d80; s2[nt][3] = d81;
#pragma unroll
            for (int e = 0; e < 4; e++) s1[nt][e] *= 0.125f;
        }

        // ---- chunk row maxes
        float cm1g = -1e30f, cm1h = -1e30f, cm2g = -1e30f, cm2h = -1e30f;
#pragma unroll
        for (int nt = 0; nt < 8; nt++) {
            cm1g = fmaxf(cm1g, fmaxf(s1[nt][0], s1[nt][1]));
            cm1h = fmaxf(cm1h, fmaxf(s1[nt][2], s1[nt][3]));
            cm2g = fmaxf(cm2g, fmaxf(s2[nt][0], s2[nt][1]));
            cm2h = fmaxf(cm2h, fmaxf(s2[nt][2], s2[nt][3]));
        }
#pragma unroll
        for (int o = 1; o <= 2; o <<= 1) {
            cm1g = fmaxf(cm1g, __shfl_xor_sync(0xffffffffu, cm1g, o));
            cm1h = fmaxf(cm1h, __shfl_xor_sync(0xffffffffu, cm1h, o));
            cm2g = fmaxf(cm2g, __shfl_xor_sync(0xffffffffu, cm2g, o));
            cm2h = fmaxf(cm2h, __shfl_xor_sync(0xffffffffu, cm2h, o));
        }

        // ---- online rescale
        float nm, al;
        nm = fmaxf(m1[0], cm1g); al = __expf(m1[0] - nm); m1[0] = nm; l1[0] *= al;
#pragma unroll
        for (int nb = 0; nb < 8; nb++) { O1[nb][0] *= al; O1[nb][1] *= al; }
        nm = fmaxf(m1[1], cm1h); al = __expf(m1[1] - nm); m1[1] = nm; l1[1] *= al;
#pragma unroll
        for (int nb = 0; nb < 8; nb++) { O1[nb][2] *= al; O1[nb][3] *= al; }
        nm = fmaxf(m2[0], cm2g); al = __expf(m2[0] - nm); m2[0] = nm; l2[0] *= al;
#pragma unroll
        for (int nb = 0; nb < 8; nb++) { O2[nb][0] *= al; O2[nb][1] *= al; }
        nm = fmaxf(m2[1], cm2h); al = __expf(m2[1] - nm); m2[1] = nm; l2[1] *= al;
#pragma unroll
        for (int nb = 0; nb < 8; nb++) { O2[nb][2] *= al; O2[nb][3] *= al; }

        // ---- exp in place + row sums
        float rs1g = 0.f, rs1h = 0.f, rs2g = 0.f, rs2h = 0.f;
#pragma unroll
        for (int nt = 0; nt < 8; nt++) {
            s1[nt][0] = __expf(s1[nt][0] - m1[0]); rs1g += s1[nt][0];
            s1[nt][1] = __expf(s1[nt][1] - m1[0]); rs1g += s1[nt][1];
            s1[nt][2] = __expf(s1[nt][2] - m1[1]); rs1h += s1[nt][2];
            s1[nt][3] = __expf(s1[nt][3] - m1[1]); rs1h += s1[nt][3];
            s2[nt][0] = __expf(s2[nt][0] - m2[0]); rs2g += s2[nt][0];
            s2[nt][1] = __expf(s2[nt][1] - m2[0]); rs2g += s2[nt][1];
            s2[nt][2] = __expf(s2[nt][2] - m2[1]); rs2h += s2[nt][2];
            s2[nt][3] = __expf(s2[nt][3] - m2[1]); rs2h += s2[nt][3];
        }
#pragma unroll
        for (int o = 1; o <= 2; o <<= 1) {
            rs1g += __shfl_xor_sync(0xffffffffu, rs1g, o);
            rs1h += __shfl_xor_sync(0xffffffffu, rs1h, o);
            rs2g += __shfl_xor_sync(0xffffffffu, rs2g, o);
            rs2h += __shfl_xor_sync(0xffffffffu, rs2h, o);
        }
        l1[0] += rs1g; l1[1] += rs1h;
        l2[0] += rs2g; l2[1] += rs2h;

        // ---- PV mma: A frags pack directly from C-layout
#pragma unroll
        for (int kb = 0; kb < 4; kb++) {
            uint32_t A1_0 = pk(s1[2 * kb][0],     s1[2 * kb][1]);
            uint32_t A1_1 = pk(s1[2 * kb][2],     s1[2 * kb][3]);
            uint32_t A1_2 = pk(s1[2 * kb + 1][0], s1[2 * kb + 1][1]);
            uint32_t A1_3 = pk(s1[2 * kb + 1][2], s1[2 * kb + 1][3]);
            uint32_t A2_0 = pk(s2[2 * kb][0],     s2[2 * kb][1]);
            uint32_t A2_1 = pk(s2[2 * kb][2],     s2[2 * kb][3]);
            uint32_t A2_2 = pk(s2[2 * kb + 1][0], s2[2 * kb + 1][1]);
            uint32_t A2_3 = pk(s2[2 * kb + 1][2], s2[2 * kb + 1][3]);

#pragma unroll
            for (int nb = 0; nb < 8; nb++) {
                uint32_t b0 = Vw[(8 * kb + tg)     * VST + nb * 8 + g];
                uint32_t b1 = Vw[(8 * kb + tg + 4) * VST + nb * 8 + g];
                mma_f16(O1[nb][0], O1[nb][1], O1[nb][2], O1[nb][3],
                        A1_0, A1_1, A1_2, A1_3, b0, b1);
                mma_f16(O2[nb][0], O2[nb][1], O2[nb][2], O2[nb][3],
                        A2_0, A2_1, A2_2, A2_3, b0, b1);
            }
        }
    }

    // ---- combine + write (fp16 AO)
    const float mixr = (tanhf(__ldg(mixp)) + 1.f) * 0.5f;
    const float w1g = (1.f - mixr) / l1[0], w1h = (1.f - mixr) / l1[1];
    const float w2g = mixr / l2[0],         w2h = mixr / l2[1];
    __half* Ao = g_AOh + (size_t)(b * L_ + i0 + wrow) * DIM_ + h * HD_;
#pragma unroll
    for (int nb = 0; nb < 8; nb++) {
        const int col = nb * 8 + 2 * tg;
        *(uint32_t*)(Ao + (size_t)g * DIM_ + col) =
            pk(O1[nb][0] * w1g + O2[nb][0] * w2g,
               O1[nb][1] * w1g + O2[nb][1] * w2g);
        *(uint32_t*)(Ao + (size_t)(g + 8) * DIM_ + col) =
            pk(O1[nb][2] * w1h + O2[nb][2] * w2h,
               O1[nb][3] * w1h + O2[nb][3] * w2h);
    }
}

// ---------------------------------------------------------------------------
extern "C" void kernel_launch(void* const* d_in, const int* in_sizes, int n_in,
                              void* d_out, int out_size)
{
    const float* seq1 = (const float*)d_in[0];
    const float* seq2 = (const float*)d_in[1];
    const float* atc1 = (const float*)d_in[2];
    const float* atc2 = (const float*)d_in[3];
    const float* Wq   = (const float*)d_in[4];
    const float* bq   = (const float*)d_in[5];
    const float* Wk   = (const float*)d_in[6];
    const float* bk   = (const float*)d_in[7];
    const float* Wv   = (const float*)d_in[8];
    const float* bv   = (const float*)d_in[9];
    const float* Wo   = (const float*)d_in[10];
    const float* bo   = (const float*)d_in[11];
    const float* U    = (const float*)d_in[12];
    const float* mixp = (const float*)d_in[13];
    float* out = (float*)d_out;

    const int M = B_ * L_;                       // 4096

    // One-time fp32 -> fp16 conversion of seq1/seq2/Wq/Wk/Wv/Wo
    cvt_f16_kernel<<<dim3(256, 1, 6), 256>>>(seq1, seq2, Wq, Wk, Wv, Wo);

    // Fused Q/K/V projections (fp16-native, KB=32)
    gemm_f16<<<dim3(DIM_ / 128, M / 128, 3), 128>>>(bq, bk, bv, nullptr, 0);

    // Fused attention (fp16-native inputs)
    attn_fused_kernel<<<dim3(L_ / 128, B_ * H_), 256>>>(atc1, atc2, U, mixp);

    // Output projection -> d_out (fp32)
    gemm_f16<<<dim3(DIM_ / 128, M / 128, 1), 128>>>(bo, nullptr, nullptr, out, 1);
}